// round 2
// baseline (speedup 1.0000x reference)
#include <cuda_runtime.h>
#include <math.h>
#include <cfloat>

// ---------------------------------------------------------------------------
// VQGAN forward, fp32, packed f32x2 FMA (Blackwell 2x fp32).
//  x:  (2,3,64,64,64)
//  enc1..3: conv k4 s2 p1 + ReLU;  enc4: 1x1 conv
//  VQ over 1024 codes / 256 dims (raw-view vectors, argmin tie -> smaller k)
//  dec1..3: convT k4 s2 p1 + ReLU (8-parity decomposition -> 2x2x2 taps)
//  dec4: conv k4 s1 p0 + tanh -> (2,3,61,61,61)
// ---------------------------------------------------------------------------

#define NB 2

__device__ float g_h1[(size_t)NB * 64 * 32 * 32 * 32];
__device__ float g_h2[(size_t)NB * 128 * 16 * 16 * 16];
__device__ float g_h3[(size_t)NB * 256 * 8 * 8 * 8];
__device__ float g_lat[(size_t)NB * 256 * 512];
__device__ float g_q[(size_t)NB * 256 * 512];
__device__ float g_d1[(size_t)NB * 256 * 16 * 16 * 16];
__device__ float g_d2[(size_t)NB * 128 * 32 * 32 * 32];
__device__ float g_d3[(size_t)NB * 64 * 64 * 64 * 64];

// ---- packed f32x2 helpers --------------------------------------------------
__device__ __forceinline__ unsigned long long pack2(float a, float b) {
    unsigned long long r;
    asm("mov.b64 %0, {%1, %2};" : "=l"(r) : "f"(a), "f"(b));
    return r;
}
__device__ __forceinline__ void fma2(unsigned long long& d,
                                     unsigned long long a, unsigned long long b) {
    asm("fma.rn.f32x2 %0, %1, %2, %0;" : "+l"(d) : "l"(a), "l"(b));
}
__device__ __forceinline__ float2 unpack2(unsigned long long v) {
    float2 r;
    asm("mov.b64 {%0, %1}, %2;" : "=f"(r.x), "=f"(r.y) : "l"(v));
    return r;
}

// ---------------------------------------------------------------------------
// conv3d k=4 s=2 p=1 + ReLU. Thread: 8 couts x P consecutive x-outputs.
// Weights staged duplicated ({w,w}) in smem -> LDS.64 broadcast operand.
// ---------------------------------------------------------------------------
template <int Cin, int Cout, int Dout, int P>
__global__ void conv_s2_relu(const float* __restrict__ in,
                             const float* __restrict__ w,
                             const float* __restrict__ bias,
                             float* __restrict__ out)
{
    constexpr int Din = 2 * Dout;
    constexpr int CI_CHUNK = (Cin < 8) ? Cin : 8;
    __shared__ float2 ws2[CI_CHUNK][8][64];

    const int tid = threadIdx.x;
    const int coBase = blockIdx.y * 8;
    const int b = blockIdx.z;
    const int s0 = blockIdx.x * (128 * P) + tid * P;   // Dout%P==0 -> same row
    const int ox0 = s0 % Dout;
    const int oy = (s0 / Dout) % Dout;
    const int oz = s0 / (Dout * Dout);

    unsigned long long acc[P / 2][8];
#pragma unroll
    for (int j = 0; j < P / 2; j++)
#pragma unroll
        for (int c = 0; c < 8; c++) acc[j][c] = 0ULL;

    const float* inB = in + (size_t)b * Cin * Din * Din * Din;

    for (int ci0 = 0; ci0 < Cin; ci0 += CI_CHUNK) {
        const int nload = CI_CHUNK * 8 * 64;
        for (int i = tid; i < nload; i += 128) {
            int ci = i / (8 * 64);
            int rem = i % (8 * 64);
            int co = rem / 64;
            int tap = rem % 64;
            float wv = w[((size_t)(coBase + co) * Cin + (ci0 + ci)) * 64 + tap];
            ws2[ci][co][tap] = make_float2(wv, wv);
        }
        __syncthreads();

#pragma unroll 1
        for (int ci = 0; ci < CI_CHUNK; ci++) {
            const float* inC = inB + (size_t)(ci0 + ci) * Din * Din * Din;
            const unsigned long long* wsu =
                reinterpret_cast<const unsigned long long*>(&ws2[ci][0][0]);
#pragma unroll
            for (int kd = 0; kd < 4; kd++) {
                const int iz = 2 * oz + kd - 1;
                if ((unsigned)iz >= (unsigned)Din) continue;
#pragma unroll
                for (int kh = 0; kh < 4; kh++) {
                    const int iy = 2 * oy + kh - 1;
                    if ((unsigned)iy >= (unsigned)Din) continue;
                    const float* row = inC + (size_t)iz * Din * Din + (size_t)iy * Din;
#pragma unroll
                    for (int kw = 0; kw < 4; kw++) {
                        const int ixb = 2 * ox0 + kw - 1;
                        float v[P];
#pragma unroll
                        for (int p = 0; p < P; p++) {
                            int ix = ixb + 2 * p;
                            v[p] = ((unsigned)ix < (unsigned)Din) ? row[ix] : 0.f;
                        }
                        unsigned long long v2[P / 2];
#pragma unroll
                        for (int j = 0; j < P / 2; j++) v2[j] = pack2(v[2 * j], v[2 * j + 1]);
                        const int tap = kd * 16 + kh * 4 + kw;
#pragma unroll
                        for (int c = 0; c < 8; c++) {
                            unsigned long long w2 = wsu[c * 64 + tap];
#pragma unroll
                            for (int j = 0; j < P / 2; j++) fma2(acc[j][c], v2[j], w2);
                        }
                    }
                }
            }
        }
        __syncthreads();
    }

#pragma unroll
    for (int c = 0; c < 8; c++) {
        float bv = bias[coBase + c];
        size_t base = (((size_t)b * Cout + coBase + c) * Dout + oz) * Dout * Dout
                      + (size_t)oy * Dout + ox0;
#pragma unroll
        for (int j = 0; j < P / 2; j++) {
            float2 r = unpack2(acc[j][c]);
            out[base + 2 * j]     = fmaxf(r.x + bv, 0.f);
            out[base + 2 * j + 1] = fmaxf(r.y + bv, 0.f);
        }
    }
}

// ---------------------------------------------------------------------------
// 1x1 conv (enc4): 256->256 over 512 spatial, per batch. No ReLU.
// ---------------------------------------------------------------------------
__global__ void conv1x1(const float* __restrict__ in, const float* __restrict__ w,
                        const float* __restrict__ bias, float* __restrict__ out)
{
    __shared__ float ws[8][256];
    const int tid = threadIdx.x;
    const int coBase = blockIdx.y * 8;
    const int b = blockIdx.z;
    const int s = blockIdx.x * 128 + tid;

    for (int i = tid; i < 8 * 256; i += 128)
        ws[i / 256][i % 256] = w[(size_t)(coBase + i / 256) * 256 + (i % 256)];
    __syncthreads();

    float acc[8];
#pragma unroll
    for (int c = 0; c < 8; c++) acc[c] = 0.f;

    const float* inB = in + (size_t)b * 256 * 512 + s;
    for (int ci = 0; ci < 256; ci++) {
        float v = inB[(size_t)ci * 512];
#pragma unroll
        for (int c = 0; c < 8; c++) acc[c] += v * ws[c][ci];
    }
#pragma unroll
    for (int c = 0; c < 8; c++)
        out[((size_t)b * 256 + coBase + c) * 512 + s] = acc[c] + bias[coBase + c];
}

// ---------------------------------------------------------------------------
// VQ (unchanged; exact expand-norm formula, argmin tie -> smaller k)
// ---------------------------------------------------------------------------
__global__ void vq_kernel(const float* __restrict__ lat, const float* __restrict__ cb,
                          float* __restrict__ q, float* __restrict__ idx_out)
{
    __shared__ float4 latS[8][64];
    __shared__ float ln[8];
    __shared__ float bd[8][128];
    __shared__ int bk[8][128];
    __shared__ int wink[8];

    const int tid = threadIdx.x;
    const int vb = blockIdx.x * 8;

    for (int i = tid; i < 8 * 64; i += 128) {
        int v = i >> 6, d4 = i & 63;
        latS[v][d4] = ((const float4*)lat)[(size_t)(vb + v) * 64 + d4];
    }
    __syncthreads();

    if (tid < 8) {
        float s = 0.f;
        for (int d4 = 0; d4 < 64; d4++) {
            float4 l = latS[tid][d4];
            s += l.x * l.x + l.y * l.y + l.z * l.z + l.w * l.w;
        }
        ln[tid] = s;
    }
    __syncthreads();

    float best[8];
    int bestk[8];
#pragma unroll
    for (int v = 0; v < 8; v++) { best[v] = FLT_MAX; bestk[v] = 0; }

    for (int j = 0; j < 8; j++) {
        const int k = tid + j * 128;
        const float4* cbr = (const float4*)(cb + (size_t)k * 256);
        float dot[8];
        float cn = 0.f;
#pragma unroll
        for (int v = 0; v < 8; v++) dot[v] = 0.f;
        for (int d4 = 0; d4 < 64; d4++) {
            float4 c = cbr[d4];
            cn += c.x * c.x + c.y * c.y + c.z * c.z + c.w * c.w;
#pragma unroll
            for (int v = 0; v < 8; v++) {
                float4 l = latS[v][d4];
                dot[v] += c.x * l.x + c.y * l.y + c.z * l.z + c.w * l.w;
            }
        }
#pragma unroll
        for (int v = 0; v < 8; v++) {
            float d2 = ln[v] - 2.f * dot[v] + cn;
            if (d2 < best[v]) { best[v] = d2; bestk[v] = k; }
        }
    }

#pragma unroll
    for (int v = 0; v < 8; v++) { bd[v][tid] = best[v]; bk[v][tid] = bestk[v]; }
    __syncthreads();
    for (int s = 64; s > 0; s >>= 1) {
        if (tid < s) {
#pragma unroll
            for (int v = 0; v < 8; v++) {
                float dB = bd[v][tid + s];
                int kB = bk[v][tid + s];
                float dA = bd[v][tid];
                int kA = bk[v][tid];
                if (dB < dA || (dB == dA && kB < kA)) { bd[v][tid] = dB; bk[v][tid] = kB; }
            }
        }
        __syncthreads();
    }
    if (tid < 8) {
        wink[tid] = bk[tid][0];
        if (idx_out) idx_out[vb + tid] = (float)bk[tid][0];
    }
    __syncthreads();

    for (int i = tid; i < 8 * 256; i += 128) {
        int v = i >> 8, c = i & 255;
        int gn = vb + v;
        int b = gn >> 9, n = gn & 511;
        q[((size_t)b * 256 + c) * 512 + n] = cb[(size_t)wink[v] * 256 + c];
    }
}

// ---------------------------------------------------------------------------
// convtranspose3d k=4 s=2 p=1 + ReLU, 8 output-parity classes (2x2x2 taps).
// Thread: 8 couts x P consecutive m-x. Duplicated weights in smem (LDS.64).
//   kernel tap index for parity r, tap bit t:  k = r ? 2-2t : 1+2t
//   input offset:                              off = r ? +t : -t
// ---------------------------------------------------------------------------
__device__ __forceinline__ int kparity(int r, int t) { return r ? (2 - 2 * t) : (1 + 2 * t); }

template <int Cin, int Cout, int Din, int P>
__global__ void convT_relu(const float* __restrict__ in, const float* __restrict__ w,
                           const float* __restrict__ bias, float* __restrict__ out)
{
    constexpr int Dout = 2 * Din;
    constexpr int CI_CHUNK = 16;
    __shared__ float2 ws2[CI_CHUNK][8][8];

    const int tid = threadIdx.x;
    const int coBase = blockIdx.y * 8;
    const int bz = blockIdx.z;
    const int b = bz >> 3;
    const int cls = bz & 7;
    const int rz = (cls >> 2) & 1, ry = (cls >> 1) & 1, rx = cls & 1;

    const int zoff1 = rz ? 1 : -1;   // tz=1 offset (tz=0 offset is 0)
    const int yoff1 = ry ? 1 : -1;
    const int xoff1 = rx ? 1 : -1;

    const int m0 = blockIdx.x * (128 * P) + tid * P;
    const int mx0 = m0 % Din;
    const int my = (m0 / Din) % Din;
    const int mz = m0 / (Din * Din);

    unsigned long long acc[P / 2][8];
#pragma unroll
    for (int j = 0; j < P / 2; j++)
#pragma unroll
        for (int c = 0; c < 8; c++) acc[j][c] = 0ULL;

    const float* inB = in + (size_t)b * Cin * Din * Din * Din;

    for (int ci0 = 0; ci0 < Cin; ci0 += CI_CHUNK) {
        for (int i = tid; i < CI_CHUNK * 64; i += 128) {
            int ci = i / 64;
            int rem = i % 64;
            int co = rem / 8;
            int t = rem % 8;
            int tz = (t >> 2) & 1, ty = (t >> 1) & 1, tx = t & 1;
            int tap = kparity(rz, tz) * 16 + kparity(ry, ty) * 4 + kparity(rx, tx);
            float wv = w[((size_t)(ci0 + ci) * Cout + coBase + co) * 64 + tap];
            ws2[ci][co][t] = make_float2(wv, wv);
        }
        __syncthreads();

#pragma unroll 1
        for (int ci = 0; ci < CI_CHUNK; ci++) {
            const float* inC = inB + (size_t)(ci0 + ci) * Din * Din * Din;
            const unsigned long long* wsu =
                reinterpret_cast<const unsigned long long*>(&ws2[ci][0][0]);
#pragma unroll
            for (int tz = 0; tz < 2; tz++) {
                const int iz = mz + (tz ? zoff1 : 0);
                if ((unsigned)iz >= (unsigned)Din) continue;
#pragma unroll
                for (int ty = 0; ty < 2; ty++) {
                    const int iy = my + (ty ? yoff1 : 0);
                    if ((unsigned)iy >= (unsigned)Din) continue;
                    const float* row = inC + (size_t)iz * Din * Din + (size_t)iy * Din;
#pragma unroll
                    for (int tx = 0; tx < 2; tx++) {
                        const int xo = tx ? xoff1 : 0;
                        float v[P];
#pragma unroll
                        for (int p = 0; p < P; p++) {
                            int ix = mx0 + p + xo;
                            v[p] = ((unsigned)ix < (unsigned)Din) ? row[ix] : 0.f;
                        }
                        unsigned long long v2[P / 2];
#pragma unroll
                        for (int j = 0; j < P / 2; j++) v2[j] = pack2(v[2 * j], v[2 * j + 1]);
                        const int t = tz * 4 + ty * 2 + tx;
#pragma unroll
                        for (int c = 0; c < 8; c++) {
                            unsigned long long w2 = wsu[c * 8 + t];
#pragma unroll
                            for (int j = 0; j < P / 2; j++) fma2(acc[j][c], v2[j], w2);
                        }
                    }
                }
            }
        }
        __syncthreads();
    }

    const int oz = 2 * mz + rz;
    const int oy = 2 * my + ry;
#pragma unroll
    for (int c = 0; c < 8; c++) {
        float bv = bias[coBase + c];
        size_t base = (((size_t)b * Cout + coBase + c) * Dout + oz) * Dout * Dout
                      + (size_t)oy * Dout;
#pragma unroll
        for (int j = 0; j < P / 2; j++) {
            float2 r = unpack2(acc[j][c]);
            out[base + 2 * (mx0 + 2 * j) + rx]     = fmaxf(r.x + bv, 0.f);
            out[base + 2 * (mx0 + 2 * j + 1) + rx] = fmaxf(r.y + bv, 0.f);
        }
    }
}

// ---------------------------------------------------------------------------
// dec4: conv3d k=4 s=1 p=0, 64->3, tanh. Thread: 3 couts x 8 consecutive x.
// ---------------------------------------------------------------------------
__global__ void conv_final_tanh(const float* __restrict__ in, const float* __restrict__ w,
                                const float* __restrict__ bias, float* __restrict__ out)
{
    __shared__ float ws[3 * 64 * 64];   // 48KB
    const int tid = threadIdx.x;
    for (int i = tid; i < 3 * 64 * 64; i += 128) ws[i] = w[i];
    __syncthreads();

    const int b = blockIdx.z;
    const int z = blockIdx.y;               // 0..60
    const int ry = tid / 8;                 // 0..15
    const int y = blockIdx.x * 16 + ry;     // 0..63
    const int x0 = (tid % 8) * 8;           // 0..56
    if (y >= 61) return;

    unsigned long long acc[3][4];
#pragma unroll
    for (int c = 0; c < 3; c++)
#pragma unroll
        for (int j = 0; j < 4; j++) acc[c][j] = 0ULL;

    const float* inB = in + (size_t)b * 64 * 64 * 64 * 64;
#pragma unroll 1
    for (int ci = 0; ci < 64; ci++) {
        const float* inC = inB + (size_t)ci * 262144;
#pragma unroll
        for (int kd = 0; kd < 4; kd++) {
            const float* pz = inC + (size_t)(z + kd) * 4096;
#pragma unroll
            for (int kh = 0; kh < 4; kh++) {
                const float* row = pz + (size_t)(y + kh) * 64;
                float v[11];
#pragma unroll
                for (int jj = 0; jj < 11; jj++) {
                    int ix = x0 + jj;
                    v[jj] = (ix < 64) ? row[ix] : 0.f;
                }
#pragma unroll
                for (int kw = 0; kw < 4; kw++) {
                    unsigned long long v2[4];
#pragma unroll
                    for (int j = 0; j < 4; j++) v2[j] = pack2(v[kw + 2 * j], v[kw + 2 * j + 1]);
#pragma unroll
                    for (int c = 0; c < 3; c++) {
                        float wv = ws[((size_t)c * 64 + ci) * 64 + kd * 16 + kh * 4 + kw];
                        unsigned long long w2 = pack2(wv, wv);
#pragma unroll
                        for (int j = 0; j < 4; j++) fma2(acc[c][j], v2[j], w2);
                    }
                }
            }
        }
    }

#pragma unroll
    for (int c = 0; c < 3; c++) {
        float bv = bias[c];
        size_t base = (((size_t)b * 3 + c) * 61 + z) * 61 * 61 + (size_t)y * 61;
#pragma unroll
        for (int j = 0; j < 4; j++) {
            float2 r = unpack2(acc[c][j]);
            int x = x0 + 2 * j;
            if (x < 61)     out[base + x]     = tanhf(r.x + bv);
            if (x + 1 < 61) out[base + x + 1] = tanhf(r.y + bv);
        }
    }
}

// ---------------------------------------------------------------------------

extern "C" void kernel_launch(void* const* d_in, const int* in_sizes, int n_in,
                              void* d_out, int out_size)
{
    const float* x   = (const float*)d_in[0];
    const float* ew1 = (const float*)d_in[1];  const float* eb1 = (const float*)d_in[2];
    const float* ew2 = (const float*)d_in[3];  const float* eb2 = (const float*)d_in[4];
    const float* ew3 = (const float*)d_in[5];  const float* eb3 = (const float*)d_in[6];
    const float* ew4 = (const float*)d_in[7];  const float* eb4 = (const float*)d_in[8];
    const float* cb  = (const float*)d_in[9];
    const float* dw1 = (const float*)d_in[10]; const float* db1 = (const float*)d_in[11];
    const float* dw2 = (const float*)d_in[12]; const float* db2 = (const float*)d_in[13];
    const float* dw3 = (const float*)d_in[14]; const float* db3 = (const float*)d_in[15];
    const float* dw4 = (const float*)d_in[16]; const float* db4 = (const float*)d_in[17];

    float* out = (float*)d_out;
    const int RECON = 2 * 3 * 61 * 61 * 61;  // 1361886
    float* idx_out = (out_size >= RECON + 1024) ? (out + RECON) : nullptr;

    float *h1, *h2, *h3, *lat, *q, *d1, *d2, *d3;
    cudaGetSymbolAddress((void**)&h1, g_h1);
    cudaGetSymbolAddress((void**)&h2, g_h2);
    cudaGetSymbolAddress((void**)&h3, g_h3);
    cudaGetSymbolAddress((void**)&lat, g_lat);
    cudaGetSymbolAddress((void**)&q, g_q);
    cudaGetSymbolAddress((void**)&d1, g_d1);
    cudaGetSymbolAddress((void**)&d2, g_d2);
    cudaGetSymbolAddress((void**)&d3, g_d3);

    // encoder
    conv_s2_relu<3, 64, 32, 8><<<dim3(32, 8, 2), 128>>>(x, ew1, eb1, h1);
    conv_s2_relu<64, 128, 16, 8><<<dim3(4, 16, 2), 128>>>(h1, ew2, eb2, h2);
    conv_s2_relu<128, 256, 8, 4><<<dim3(1, 32, 2), 128>>>(h2, ew3, eb3, h3);
    conv1x1<<<dim3(4, 32, 2), 128>>>(h3, ew4, eb4, lat);

    // vector quantization (also writes idx tail of output)
    vq_kernel<<<128, 128>>>(lat, cb, q, idx_out);

    // decoder
    convT_relu<256, 256, 8, 4><<<dim3(1, 32, 16), 128>>>(q, dw1, db1, d1);
    convT_relu<256, 128, 16, 8><<<dim3(4, 16, 16), 128>>>(d1, dw2, db2, d2);
    convT_relu<128, 64, 32, 8><<<dim3(32, 8, 16), 128>>>(d2, dw3, db3, d3);
    conv_final_tanh<<<dim3(4, 61, 2), 128>>>(d3, dw4, db4, out);
}

// round 3
// speedup vs baseline: 1.3571x; 1.3571x over previous
#include <cuda_runtime.h>
#include <math.h>
#include <cfloat>

// ---------------------------------------------------------------------------
// VQGAN forward, fp32 scalar FFMA, row-shared loads + x-interior fast path.
//  x:  (2,3,64,64,64)
//  enc1..3: conv k4 s2 p1 + ReLU;  enc4: 1x1 conv
//  VQ over 1024 codes / 256 dims (raw-view vectors, argmin tie -> smaller k)
//  dec1..3: convT k4 s2 p1 + ReLU (8-parity decomposition -> 2x2x2 taps)
//  dec4: conv k4 s1 p0 + tanh -> (2,3,61,61,61)
// ---------------------------------------------------------------------------

#define NB 2

__device__ float g_h1[(size_t)NB * 64 * 32 * 32 * 32];
__device__ float g_h2[(size_t)NB * 128 * 16 * 16 * 16];
__device__ float g_h3[(size_t)NB * 256 * 8 * 8 * 8];
__device__ float g_lat[(size_t)NB * 256 * 512];
__device__ float g_q[(size_t)NB * 256 * 512];
__device__ float g_d1[(size_t)NB * 256 * 16 * 16 * 16];
__device__ float g_d2[(size_t)NB * 128 * 32 * 32 * 32];
__device__ float g_d3[(size_t)NB * 64 * 64 * 64 * 64];

// ---------------------------------------------------------------------------
// conv3d k=4 s=2 p=1 + ReLU. Thread: TC couts x P consecutive x-outputs.
// Per (kd,kh) row: load union of 2P+2 input values once, reuse for all 4 kw.
// ---------------------------------------------------------------------------
template <int Cin, int Cout, int Dout, int TC, int P>
__global__ void conv_s2_relu(const float* __restrict__ in,
                             const float* __restrict__ w,
                             const float* __restrict__ bias,
                             float* __restrict__ out)
{
    constexpr int Din = 2 * Dout;
    constexpr int CI_CHUNK = (Cin < 16) ? Cin : 16;
    constexpr int NV = 2 * P + 2;
    __shared__ float ws[CI_CHUNK][TC][64];

    const int tid = threadIdx.x;
    const int coBase = blockIdx.y * TC;
    const int b = blockIdx.z;
    const int s0 = blockIdx.x * (128 * P) + tid * P;   // Dout%P==0 -> same row
    const int ox0 = s0 % Dout;
    const int oy = (s0 / Dout) % Dout;
    const int oz = s0 / (Dout * Dout);
    const int ixb = 2 * ox0 - 1;                        // base x of vals[]
    const bool xin = (ixb >= 0) && (ixb + NV - 1 <= Din - 1);

    float acc[P][TC];
#pragma unroll
    for (int p = 0; p < P; p++)
#pragma unroll
        for (int c = 0; c < TC; c++) acc[p][c] = 0.f;

    const float* inB = in + (size_t)b * Cin * Din * Din * Din;

    for (int ci0 = 0; ci0 < Cin; ci0 += CI_CHUNK) {
        const int nload = CI_CHUNK * TC * 64;
        for (int i = tid; i < nload; i += 128) {
            int ci = i / (TC * 64);
            int rem = i % (TC * 64);
            int co = rem / 64;
            int tap = rem % 64;
            ws[ci][co][tap] = w[((size_t)(coBase + co) * Cin + (ci0 + ci)) * 64 + tap];
        }
        __syncthreads();

#pragma unroll 1
        for (int ci = 0; ci < CI_CHUNK; ci++) {
            const float* inC = inB + (size_t)(ci0 + ci) * Din * Din * Din;
#pragma unroll
            for (int kd = 0; kd < 4; kd++) {
                const int iz = 2 * oz + kd - 1;
                if ((unsigned)iz >= (unsigned)Din) continue;
#pragma unroll
                for (int kh = 0; kh < 4; kh++) {
                    const int iy = 2 * oy + kh - 1;
                    if ((unsigned)iy >= (unsigned)Din) continue;
                    const float* row = inC + (size_t)iz * Din * Din + (size_t)iy * Din + ixb;

                    float vals[NV];
                    if (xin) {
#pragma unroll
                        for (int j = 0; j < NV; j++) vals[j] = row[j];
                    } else {
#pragma unroll
                        for (int j = 0; j < NV; j++) {
                            int ix = ixb + j;
                            vals[j] = ((unsigned)ix < (unsigned)Din) ? row[j] : 0.f;
                        }
                    }
#pragma unroll
                    for (int kw = 0; kw < 4; kw++) {
                        const int tap = kd * 16 + kh * 4 + kw;
#pragma unroll
                        for (int c = 0; c < TC; c++) {
                            const float wv = ws[ci][c][tap];
#pragma unroll
                            for (int p = 0; p < P; p++)
                                acc[p][c] = fmaf(vals[kw + 2 * p], wv, acc[p][c]);
                        }
                    }
                }
            }
        }
        __syncthreads();
    }

#pragma unroll
    for (int c = 0; c < TC; c++) {
        float bv = bias[coBase + c];
        size_t base = (((size_t)b * Cout + coBase + c) * Dout + oz) * Dout * Dout
                      + (size_t)oy * Dout + ox0;
#pragma unroll
        for (int p = 0; p < P; p++) out[base + p] = fmaxf(acc[p][c] + bv, 0.f);
    }
}

// ---------------------------------------------------------------------------
// 1x1 conv (enc4): 256->256 over 512 spatial, per batch. No ReLU.
// ---------------------------------------------------------------------------
__global__ void conv1x1(const float* __restrict__ in, const float* __restrict__ w,
                        const float* __restrict__ bias, float* __restrict__ out)
{
    __shared__ float ws[8][256];
    const int tid = threadIdx.x;
    const int coBase = blockIdx.y * 8;
    const int b = blockIdx.z;
    const int s = blockIdx.x * 128 + tid;

    for (int i = tid; i < 8 * 256; i += 128)
        ws[i / 256][i % 256] = w[(size_t)(coBase + i / 256) * 256 + (i % 256)];
    __syncthreads();

    float acc[8];
#pragma unroll
    for (int c = 0; c < 8; c++) acc[c] = 0.f;

    const float* inB = in + (size_t)b * 256 * 512 + s;
    for (int ci = 0; ci < 256; ci++) {
        float v = inB[(size_t)ci * 512];
#pragma unroll
        for (int c = 0; c < 8; c++) acc[c] += v * ws[c][ci];
    }
#pragma unroll
    for (int c = 0; c < 8; c++)
        out[((size_t)b * 256 + coBase + c) * 512 + s] = acc[c] + bias[coBase + c];
}

// ---------------------------------------------------------------------------
// VQ (exact expand-norm formula, argmin tie -> smaller k)
// ---------------------------------------------------------------------------
__global__ void vq_kernel(const float* __restrict__ lat, const float* __restrict__ cb,
                          float* __restrict__ q, float* __restrict__ idx_out)
{
    __shared__ float4 latS[8][64];
    __shared__ float ln[8];
    __shared__ float bd[8][128];
    __shared__ int bk[8][128];
    __shared__ int wink[8];

    const int tid = threadIdx.x;
    const int vb = blockIdx.x * 8;

    for (int i = tid; i < 8 * 64; i += 128) {
        int v = i >> 6, d4 = i & 63;
        latS[v][d4] = ((const float4*)lat)[(size_t)(vb + v) * 64 + d4];
    }
    __syncthreads();

    if (tid < 8) {
        float s = 0.f;
        for (int d4 = 0; d4 < 64; d4++) {
            float4 l = latS[tid][d4];
            s += l.x * l.x + l.y * l.y + l.z * l.z + l.w * l.w;
        }
        ln[tid] = s;
    }
    __syncthreads();

    float best[8];
    int bestk[8];
#pragma unroll
    for (int v = 0; v < 8; v++) { best[v] = FLT_MAX; bestk[v] = 0; }

    for (int j = 0; j < 8; j++) {
        const int k = tid + j * 128;
        const float4* cbr = (const float4*)(cb + (size_t)k * 256);
        float dot[8];
        float cn = 0.f;
#pragma unroll
        for (int v = 0; v < 8; v++) dot[v] = 0.f;
        for (int d4 = 0; d4 < 64; d4++) {
            float4 c = cbr[d4];
            cn += c.x * c.x + c.y * c.y + c.z * c.z + c.w * c.w;
#pragma unroll
            for (int v = 0; v < 8; v++) {
                float4 l = latS[v][d4];
                dot[v] += c.x * l.x + c.y * l.y + c.z * l.z + c.w * l.w;
            }
        }
#pragma unroll
        for (int v = 0; v < 8; v++) {
            float d2 = ln[v] - 2.f * dot[v] + cn;
            if (d2 < best[v]) { best[v] = d2; bestk[v] = k; }
        }
    }

#pragma unroll
    for (int v = 0; v < 8; v++) { bd[v][tid] = best[v]; bk[v][tid] = bestk[v]; }
    __syncthreads();
    for (int s = 64; s > 0; s >>= 1) {
        if (tid < s) {
#pragma unroll
            for (int v = 0; v < 8; v++) {
                float dB = bd[v][tid + s];
                int kB = bk[v][tid + s];
                float dA = bd[v][tid];
                int kA = bk[v][tid];
                if (dB < dA || (dB == dA && kB < kA)) { bd[v][tid] = dB; bk[v][tid] = kB; }
            }
        }
        __syncthreads();
    }
    if (tid < 8) {
        wink[tid] = bk[tid][0];
        if (idx_out) idx_out[vb + tid] = (float)bk[tid][0];
    }
    __syncthreads();

    for (int i = tid; i < 8 * 256; i += 128) {
        int v = i >> 8, c = i & 255;
        int gn = vb + v;
        int b = gn >> 9, n = gn & 511;
        q[((size_t)b * 256 + c) * 512 + n] = cb[(size_t)wink[v] * 256 + c];
    }
}

// ---------------------------------------------------------------------------
// convtranspose3d k=4 s=2 p=1 + ReLU, 8 output-parity classes (2x2x2 taps).
// Per (tz,ty) row: load union of P+2 values once, reuse for both tx taps.
//   kernel tap index for parity r, tap bit t:  k = r ? 2-2t : 1+2t
//   input offset:                              off = r ? +t : -t
// ---------------------------------------------------------------------------
__device__ __forceinline__ int kparity(int r, int t) { return r ? (2 - 2 * t) : (1 + 2 * t); }

template <int Cin, int Cout, int Din, int TC, int P>
__global__ void convT_relu(const float* __restrict__ in, const float* __restrict__ w,
                           const float* __restrict__ bias, float* __restrict__ out)
{
    constexpr int Dout = 2 * Din;
    constexpr int CI_CHUNK = 16;
    constexpr int NV = P + 2;
    __shared__ float ws[CI_CHUNK][TC][8];

    const int tid = threadIdx.x;
    const int coBase = blockIdx.y * TC;
    const int bz = blockIdx.z;
    const int b = bz >> 3;
    const int cls = bz & 7;
    const int rz = (cls >> 2) & 1, ry = (cls >> 1) & 1, rx = cls & 1;

    const int zoff1 = rz ? 1 : -1;   // tz=1 offset (tz=0 offset is 0)
    const int yoff1 = ry ? 1 : -1;
    // x tap offsets: tx=0 -> 0, tx=1 -> rx?+1:-1. vals[] covers mx0-1..mx0+P.
    const int xsh0 = 1;              // vals index shift for offset 0
    const int xsh1 = rx ? 2 : 0;     // vals index shift for tx=1

    const int m0 = blockIdx.x * (128 * P) + tid * P;
    const int mx0 = m0 % Din;
    const int my = (m0 / Din) % Din;
    const int mz = m0 / (Din * Din);
    const bool xin = (mx0 >= 1) && (mx0 + P <= Din - 1);

    float acc[P][TC];
#pragma unroll
    for (int p = 0; p < P; p++)
#pragma unroll
        for (int c = 0; c < TC; c++) acc[p][c] = 0.f;

    const float* inB = in + (size_t)b * Cin * Din * Din * Din;

    for (int ci0 = 0; ci0 < Cin; ci0 += CI_CHUNK) {
        for (int i = tid; i < CI_CHUNK * TC * 8; i += 128) {
            int ci = i / (TC * 8);
            int rem = i % (TC * 8);
            int co = rem / 8;
            int t = rem % 8;
            int tz = (t >> 2) & 1, ty = (t >> 1) & 1, tx = t & 1;
            int tap = kparity(rz, tz) * 16 + kparity(ry, ty) * 4 + kparity(rx, tx);
            ws[ci][co][t] = w[((size_t)(ci0 + ci) * Cout + coBase + co) * 64 + tap];
        }
        __syncthreads();

#pragma unroll 1
        for (int ci = 0; ci < CI_CHUNK; ci++) {
            const float* inC = inB + (size_t)(ci0 + ci) * Din * Din * Din;
#pragma unroll
            for (int tz = 0; tz < 2; tz++) {
                const int iz = mz + (tz ? zoff1 : 0);
                if ((unsigned)iz >= (unsigned)Din) continue;
#pragma unroll
                for (int ty = 0; ty < 2; ty++) {
                    const int iy = my + (ty ? yoff1 : 0);
                    if ((unsigned)iy >= (unsigned)Din) continue;
                    const float* row = inC + (size_t)iz * Din * Din + (size_t)iy * Din + mx0 - 1;

                    float vals[NV];
                    if (xin) {
#pragma unroll
                        for (int j = 0; j < NV; j++) vals[j] = row[j];
                    } else {
#pragma unroll
                        for (int j = 0; j < NV; j++) {
                            int ix = mx0 - 1 + j;
                            vals[j] = ((unsigned)ix < (unsigned)Din) ? row[j] : 0.f;
                        }
                    }
#pragma unroll
                    for (int tx = 0; tx < 2; tx++) {
                        const int sh = tx ? xsh1 : xsh0;
                        const int t = tz * 4 + ty * 2 + tx;
#pragma unroll
                        for (int c = 0; c < TC; c++) {
                            const float wv = ws[ci][c][t];
#pragma unroll
                            for (int p = 0; p < P; p++)
                                acc[p][c] = fmaf(vals[p + sh], wv, acc[p][c]);
                        }
                    }
                }
            }
        }
        __syncthreads();
    }

    const int oz = 2 * mz + rz;
    const int oy = 2 * my + ry;
#pragma unroll
    for (int c = 0; c < TC; c++) {
        float bv = bias[coBase + c];
        size_t base = (((size_t)b * Cout + coBase + c) * Dout + oz) * Dout * Dout
                      + (size_t)oy * Dout + rx;
#pragma unroll
        for (int p = 0; p < P; p++)
            out[base + 2 * (mx0 + p)] = fmaxf(acc[p][c] + bv, 0.f);
    }
}

// ---------------------------------------------------------------------------
// dec4: conv3d k=4 s=1 p=0, 64->3, + tanh.  (2,64,64^3) -> (2,3,61^3).
// ---------------------------------------------------------------------------
__global__ void conv_final_tanh(const float* __restrict__ in, const float* __restrict__ w,
                                const float* __restrict__ bias, float* __restrict__ out)
{
    __shared__ float ws[3 * 64 * 64];   // 48KB
    const int tid = threadIdx.x;
    for (int i = tid; i < 3 * 64 * 64; i += 128) ws[i] = w[i];
    __syncthreads();

    const int b = blockIdx.z;
    const int z = blockIdx.y;           // 0..60
    const int ry = tid / 16;            // 0..7
    const int quad = tid % 16;          // 0..15
    const int y = blockIdx.x * 8 + ry;  // 0..63
    const int x0 = quad * 4;            // 0..60
    if (y >= 61) return;

    float acc[3][4];
#pragma unroll
    for (int c = 0; c < 3; c++)
#pragma unroll
        for (int p = 0; p < 4; p++) acc[c][p] = 0.f;

    const float* inB = in + (size_t)b * 64 * 64 * 64 * 64;
#pragma unroll 1
    for (int ci = 0; ci < 64; ci++) {
        const float* inC = inB + (size_t)ci * 262144;
#pragma unroll
        for (int kd = 0; kd < 4; kd++) {
            const float* pz = inC + (size_t)(z + kd) * 4096;
#pragma unroll
            for (int kh = 0; kh < 4; kh++) {
                const float* row = pz + (size_t)(y + kh) * 64;
                float v[7];
#pragma unroll
                for (int j = 0; j < 7; j++) {
                    int ix = x0 + j;
                    v[j] = (ix < 64) ? row[ix] : 0.f;
                }
#pragma unroll
                for (int kw = 0; kw < 4; kw++) {
#pragma unroll
                    for (int c = 0; c < 3; c++) {
                        float wv = ws[((size_t)c * 64 + ci) * 64 + kd * 16 + kh * 4 + kw];
#pragma unroll
                        for (int p = 0; p < 4; p++) acc[c][p] = fmaf(v[kw + p], wv, acc[c][p]);
                    }
                }
            }
        }
    }

#pragma unroll
    for (int c = 0; c < 3; c++) {
        float bv = bias[c];
        size_t base = (((size_t)b * 3 + c) * 61 + z) * 61 * 61 + (size_t)y * 61;
#pragma unroll
        for (int p = 0; p < 4; p++) {
            int x = x0 + p;
            if (x < 61) out[base + x] = tanhf(acc[c][p] + bv);
        }
    }
}

// ---------------------------------------------------------------------------

extern "C" void kernel_launch(void* const* d_in, const int* in_sizes, int n_in,
                              void* d_out, int out_size)
{
    const float* x   = (const float*)d_in[0];
    const float* ew1 = (const float*)d_in[1];  const float* eb1 = (const float*)d_in[2];
    const float* ew2 = (const float*)d_in[3];  const float* eb2 = (const float*)d_in[4];
    const float* ew3 = (const float*)d_in[5];  const float* eb3 = (const float*)d_in[6];
    const float* ew4 = (const float*)d_in[7];  const float* eb4 = (const float*)d_in[8];
    const float* cb  = (const float*)d_in[9];
    const float* dw1 = (const float*)d_in[10]; const float* db1 = (const float*)d_in[11];
    const float* dw2 = (const float*)d_in[12]; const float* db2 = (const float*)d_in[13];
    const float* dw3 = (const float*)d_in[14]; const float* db3 = (const float*)d_in[15];
    const float* dw4 = (const float*)d_in[16]; const float* db4 = (const float*)d_in[17];

    float* out = (float*)d_out;
    const int RECON = 2 * 3 * 61 * 61 * 61;  // 1361886
    float* idx_out = (out_size >= RECON + 1024) ? (out + RECON) : nullptr;

    float *h1, *h2, *h3, *lat, *q, *d1, *d2, *d3;
    cudaGetSymbolAddress((void**)&h1, g_h1);
    cudaGetSymbolAddress((void**)&h2, g_h2);
    cudaGetSymbolAddress((void**)&h3, g_h3);
    cudaGetSymbolAddress((void**)&lat, g_lat);
    cudaGetSymbolAddress((void**)&q, g_q);
    cudaGetSymbolAddress((void**)&d1, g_d1);
    cudaGetSymbolAddress((void**)&d2, g_d2);
    cudaGetSymbolAddress((void**)&d3, g_d3);

    // encoder
    conv_s2_relu<3, 64, 32, 8, 4><<<dim3(64, 8, 2), 128>>>(x, ew1, eb1, h1);
    conv_s2_relu<64, 128, 16, 8, 4><<<dim3(8, 16, 2), 128>>>(h1, ew2, eb2, h2);
    conv_s2_relu<128, 256, 8, 4, 4><<<dim3(1, 64, 2), 128>>>(h2, ew3, eb3, h3);
    conv1x1<<<dim3(4, 32, 2), 128>>>(h3, ew4, eb4, lat);

    // vector quantization (also writes idx tail of output)
    vq_kernel<<<128, 128>>>(lat, cb, q, idx_out);

    // decoder
    convT_relu<256, 256, 8, 8, 2><<<dim3(2, 32, 16), 128>>>(q, dw1, db1, d1);
    convT_relu<256, 128, 16, 8, 4><<<dim3(8, 16, 16), 128>>>(d1, dw2, db2, d2);
    convT_relu<128, 64, 32, 8, 4><<<dim3(64, 8, 16), 128>>>(d2, dw3, db3, d3);
    conv_final_tanh<<<dim3(8, 61, 2), 128>>>(d3, dw4, db4, out);
}